// round 13
// baseline (speedup 1.0000x reference)
#include <cuda_runtime.h>
#include <cuda_fp16.h>
#include <cstdint>

// ---------------------------------------------------------------------------
// GCN 3-layer: CSR-gather over dinv-prescaled fp16 rows + fp16 2-split HMMA
// GEMM, with two-level stream overlap:
//   - CSR scan/fill  ||  GEMM1
//   - gather_k chunk1  ||  GEMM_{k+1} chunk0   (h16 double-buffered)
// out = GCNConv3(relu(GCNConv2(relu(GCNConv1(x)))))
// ---------------------------------------------------------------------------

#define MAXN 100000
#define MAXE 1600000
#define SCAN_B 1024

__device__ __align__(16) __half g_hA[MAXN * 128];   // h16 buffer A
__device__ __align__(16) __half g_hB[MAXN * 128];   // h16 buffer B
__device__ __align__(16) float g_a[MAXN * 128];     // gather accumulator (fp32)
__device__ float g_dinv[MAXN];
__device__ int g_cnt[MAXN];
__device__ int g_fill[MAXN];
__device__ int g_rowptr[MAXN];
__device__ int g_incl[MAXN];
__device__ int g_bsum[256];
__device__ int g_csr[MAXE];
__device__ int g_is64;

__device__ __align__(16) __half g_w1h[128 * 128], g_w1l[128 * 128];
__device__ __align__(16) __half g_w2h[128 * 128], g_w2l[128 * 128];
__device__ __align__(16) __half g_w3h[64 * 128],  g_w3l[64 * 128];

static cudaStream_t g_s2;
static cudaEvent_t g_evf, g_evcsr, g_ev1, g_ev2, g_ev3, g_ev4;
static bool g_stream_init = []() {
    cudaStreamCreateWithFlags(&g_s2, cudaStreamNonBlocking);
    cudaEventCreateWithFlags(&g_evf, cudaEventDisableTiming);
    cudaEventCreateWithFlags(&g_evcsr, cudaEventDisableTiming);
    cudaEventCreateWithFlags(&g_ev1, cudaEventDisableTiming);
    cudaEventCreateWithFlags(&g_ev2, cudaEventDisableTiming);
    cudaEventCreateWithFlags(&g_ev3, cudaEventDisableTiming);
    cudaEventCreateWithFlags(&g_ev4, cudaEventDisableTiming);
    return true;
}();

// ---------------------------------------------------------------------------
// helpers
// ---------------------------------------------------------------------------
__device__ __forceinline__ void split_h(float v, __half& h, __half& l) {
    h = __float2half_rn(v);
    l = __float2half_rn(v - __half2float(h));
}

__device__ __forceinline__ void mma_f16(float* c, const unsigned* a,
                                        const unsigned* b) {
    asm("mma.sync.aligned.m16n8k16.row.col.f32.f16.f16.f32 "
        "{%0,%1,%2,%3},{%4,%5,%6,%7},{%8,%9},{%0,%1,%2,%3};"
        : "+f"(c[0]), "+f"(c[1]), "+f"(c[2]), "+f"(c[3])
        : "r"(a[0]), "r"(a[1]), "r"(a[2]), "r"(a[3]), "r"(b[0]), "r"(b[1]));
}

// fused weight pre-split (one launch for all three W)
__global__ void wconv_all_kernel(const float* __restrict__ W1,
                                 const float* __restrict__ W2,
                                 const float* __restrict__ W3,
                                 __half* __restrict__ w1h, __half* __restrict__ w1l,
                                 __half* __restrict__ w2h, __half* __restrict__ w2l,
                                 __half* __restrict__ w3h, __half* __restrict__ w3l) {
    int i = blockIdx.x * blockDim.x + threadIdx.x;
    __half h, l;
    if (i < 16384) {
        split_h(W1[i], h, l); w1h[i] = h; w1l[i] = l;
    } else if (i < 32768) {
        int j = i - 16384;
        split_h(W2[j], h, l); w2h[j] = h; w2l[j] = l;
    } else if (i < 40960) {
        int j = i - 32768;
        split_h(W3[j], h, l); w3h[j] = h; w3l[j] = l;
    }
}

// fused dtype probe: one block, thread 0 inits, all threads sample
__global__ void probe_kernel(const unsigned* __restrict__ ei) {
    if (threadIdx.x == 0) g_is64 = 1;
    __syncthreads();
    if (ei[2 * threadIdx.x + 1] != 0) atomicAnd(&g_is64, 0);
}

__device__ __forceinline__ void load_edge(const void* ei, int e, int g, int is64,
                                          int& s, int& d) {
    if (is64) {
        const long long* p = (const long long*)ei;
        s = (int)p[g];
        d = (int)p[e + g];
    } else {
        const int* p = (const int*)ei;
        s = p[g];
        d = p[e + g];
    }
}

// ---------------------------------------------------------------------------
// CSR build
// ---------------------------------------------------------------------------
__global__ void zero1_kernel(int* __restrict__ a, int n) {
    int i = blockIdx.x * blockDim.x + threadIdx.x;
    if (i < n) a[i] = 0;
}

// dst-only read (src stream untouched -> half the bytes)
__global__ void count_kernel(const void* __restrict__ ei, int* __restrict__ cnt,
                             int e, int n) {
    int i = blockIdx.x * blockDim.x + threadIdx.x;
    if (i >= e) return;
    int d;
    if (g_is64) d = (int)((const long long*)ei)[e + i];
    else        d = ((const int*)ei)[e + i];
    if ((unsigned)d < (unsigned)n) atomicAdd(&cnt[d], 1);
}

__global__ void dinv_kernel(const int* __restrict__ cnt, float* __restrict__ dinv,
                            int n) {
    int i = blockIdx.x * blockDim.x + threadIdx.x;
    if (i < n) dinv[i] = rsqrtf((float)cnt[i] + 1.0f);
}

__global__ __launch_bounds__(SCAN_B) void scan_block_kernel(
    const int* __restrict__ cnt, int* __restrict__ incl, int* __restrict__ bsum,
    int n) {
    __shared__ int sm[SCAN_B];
    int i = blockIdx.x * SCAN_B + threadIdx.x;
    int v = (i < n) ? cnt[i] : 0;
    sm[threadIdx.x] = v;
    __syncthreads();
#pragma unroll
    for (int off = 1; off < SCAN_B; off <<= 1) {
        int t = (threadIdx.x >= off) ? sm[threadIdx.x - off] : 0;
        __syncthreads();
        sm[threadIdx.x] += t;
        __syncthreads();
    }
    if (i < n) incl[i] = sm[threadIdx.x];
    if (threadIdx.x == SCAN_B - 1) bsum[blockIdx.x] = sm[SCAN_B - 1];
}

__global__ __launch_bounds__(256) void scan_bsum_kernel(int* __restrict__ bsum,
                                                        int nb) {
    __shared__ int sm[256];
    int v = (threadIdx.x < nb) ? bsum[threadIdx.x] : 0;
    sm[threadIdx.x] = v;
    __syncthreads();
#pragma unroll
    for (int off = 1; off < 256; off <<= 1) {
        int t = (threadIdx.x >= off) ? sm[threadIdx.x - off] : 0;
        __syncthreads();
        sm[threadIdx.x] += t;
        __syncthreads();
    }
    if (threadIdx.x < nb) bsum[threadIdx.x] = sm[threadIdx.x] - v;
}

__global__ void scan_final_kernel(const int* __restrict__ incl,
                                  const int* __restrict__ cnt,
                                  const int* __restrict__ bsum,
                                  int* __restrict__ rowptr,
                                  int* __restrict__ fill, int n) {
    int i = blockIdx.x * blockDim.x + threadIdx.x;
    if (i < n) {
        int rp = incl[i] - cnt[i] + bsum[i / SCAN_B];
        rowptr[i] = rp;
        fill[i] = rp;
    }
}

__global__ void fill_csr_kernel(const void* __restrict__ ei,
                                int* __restrict__ fill, int* __restrict__ csr,
                                int e, int n) {
    int i = blockIdx.x * blockDim.x + threadIdx.x;
    if (i >= e) return;
    int s, d;
    load_edge(ei, e, i, g_is64, s, d);
    if ((unsigned)s >= (unsigned)n || (unsigned)d >= (unsigned)n) return;
    int pos = atomicAdd(&fill[d], 1);
    csr[pos] = s;
}

// ---------------------------------------------------------------------------
// fp16 2-split HMMA GEMM over row range [row_off, row_off + 128*gridDim):
// H16[r,:] = fp16( dinv[r] * (act(X[r,:]) @ W^T) )
// ---------------------------------------------------------------------------
template <int COLS, bool RELU>
__global__ __launch_bounds__(256) void gemm_tc_kernel(
    const float* __restrict__ X, const __half* __restrict__ Wh,
    const __half* __restrict__ Wl, const float* __restrict__ dinv,
    __half* __restrict__ H, int n, int row_off) {
    __shared__ __half xs_h[128][40], xs_l[128][40];
    __shared__ __half ws_h[COLS][40], ws_l[COLS][40];

    constexpr int WM = (COLS == 128) ? 2 : 1;
    const int t = threadIdx.x;
    const int wid = t >> 5;
    const int lane = t & 31;
    const int gid = lane >> 2;
    const int tig = lane & 3;
    const int row0 = row_off + blockIdx.x * 128;

    int wm0, wn0;
    if (COLS == 128) { wm0 = (wid >> 1) * 32; wn0 = (wid & 1) * 64; }
    else             { wm0 = wid * 16;        wn0 = 0; }

    float acc[WM][8][4];
#pragma unroll
    for (int mt = 0; mt < WM; mt++)
#pragma unroll
        for (int nt = 0; nt < 8; nt++)
#pragma unroll
            for (int i = 0; i < 4; i++) acc[mt][nt][i] = 0.0f;

    for (int kb = 0; kb < 128; kb += 32) {
        for (int idx = t; idx < 128 * 32; idx += 256) {
            int r = idx >> 5, k = idx & 31;
            int row = row0 + r;
            float v = 0.0f;
            if (row < n) {
                v = X[row * 128 + kb + k];
                if (RELU) v = fmaxf(v, 0.0f);
            }
            __half h, l;
            split_h(v, h, l);
            xs_h[r][k] = h;
            xs_l[r][k] = l;
        }
        for (int idx = t; idx < COLS * 32; idx += 256) {
            int c = idx >> 5, k = idx & 31;
            ws_h[c][k] = Wh[c * 128 + kb + k];
            ws_l[c][k] = Wl[c * 128 + kb + k];
        }
        __syncthreads();

#pragma unroll
        for (int ks = 0; ks < 2; ks++) {
            const int k0 = ks * 16;
            unsigned ah[WM][4], al[WM][4];
#pragma unroll
            for (int mt = 0; mt < WM; mt++) {
                int r = wm0 + mt * 16 + gid;
                ah[mt][0] = *reinterpret_cast<const unsigned*>(&xs_h[r][k0 + tig * 2]);
                ah[mt][1] = *reinterpret_cast<const unsigned*>(&xs_h[r + 8][k0 + tig * 2]);
                ah[mt][2] = *reinterpret_cast<const unsigned*>(&xs_h[r][k0 + tig * 2 + 8]);
                ah[mt][3] = *reinterpret_cast<const unsigned*>(&xs_h[r + 8][k0 + tig * 2 + 8]);
                al[mt][0] = *reinterpret_cast<const unsigned*>(&xs_l[r][k0 + tig * 2]);
                al[mt][1] = *reinterpret_cast<const unsigned*>(&xs_l[r + 8][k0 + tig * 2]);
                al[mt][2] = *reinterpret_cast<const unsigned*>(&xs_l[r][k0 + tig * 2 + 8]);
                al[mt][3] = *reinterpret_cast<const unsigned*>(&xs_l[r + 8][k0 + tig * 2 + 8]);
            }
#pragma unroll
            for (int nt = 0; nt < 8; nt++) {
                int c = wn0 + nt * 8 + gid;
                unsigned bh[2], bl[2];
                bh[0] = *reinterpret_cast<const unsigned*>(&ws_h[c][k0 + tig * 2]);
                bh[1] = *reinterpret_cast<const unsigned*>(&ws_h[c][k0 + tig * 2 + 8]);
                bl[0] = *reinterpret_cast<const unsigned*>(&ws_l[c][k0 + tig * 2]);
                bl[1] = *reinterpret_cast<const unsigned*>(&ws_l[c][k0 + tig * 2 + 8]);
#pragma unroll
                for (int mt = 0; mt < WM; mt++) {
                    mma_f16(acc[mt][nt], ah[mt], bl);
                    mma_f16(acc[mt][nt], al[mt], bh);
                    mma_f16(acc[mt][nt], ah[mt], bh);
                }
            }
        }
        __syncthreads();
    }

#pragma unroll
    for (int mt = 0; mt < WM; mt++) {
        int r = row0 + wm0 + mt * 16 + gid;
        float d0 = (r < n) ? dinv[r] : 0.0f;
        float d1 = (r + 8 < n) ? dinv[r + 8] : 0.0f;
#pragma unroll
        for (int nt = 0; nt < 8; nt++) {
            int c = wn0 + nt * 8 + tig * 2;
            if (r < n)
                *reinterpret_cast<__half2*>(H + (size_t)r * COLS + c) =
                    __floats2half2_rn(acc[mt][nt][0] * d0, acc[mt][nt][1] * d0);
            if (r + 8 < n)
                *reinterpret_cast<__half2*>(H + (size_t)(r + 8) * COLS + c) =
                    __floats2half2_rn(acc[mt][nt][2] * d1, acc[mt][nt][3] * d1);
        }
    }
}

// ---------------------------------------------------------------------------
// gather over node range [n0, n1): A[d] = b + dinv[d]*( H'[d] + sum H'[src] )
// ---------------------------------------------------------------------------
__global__ __launch_bounds__(256) void gather128_kernel(
    const int* __restrict__ csr, const int* __restrict__ rowptr,
    const int* __restrict__ cnt, const float* __restrict__ dinv,
    const __half* __restrict__ H, const float* __restrict__ b,
    float* __restrict__ A, int n0, int n1) {
    int d = n0 + ((blockIdx.x * blockDim.x + threadIdx.x) >> 5);
    int lane = threadIdx.x & 31;
    if (d >= n1) return;
    const int start = rowptr[d];
    const int c = cnt[d];

    float4 acc;
    {
        uint2 u = reinterpret_cast<const uint2*>(H + (size_t)d * 128)[lane];
        float2 lo = __half22float2(*reinterpret_cast<__half2*>(&u.x));
        float2 hi = __half22float2(*reinterpret_cast<__half2*>(&u.y));
        acc.x = lo.x; acc.y = lo.y; acc.z = hi.x; acc.w = hi.y;
    }

    for (int j0 = 0; j0 < c; j0 += 32) {
        int s = (j0 + lane < c) ? csr[start + j0 + lane] : 0;
        int m = min(32, c - j0);
#pragma unroll 8
        for (int k = 0; k < m; k++) {
            int sk = __shfl_sync(0xffffffffu, s, k);
            uint2 u = reinterpret_cast<const uint2*>(H + (size_t)sk * 128)[lane];
            float2 lo = __half22float2(*reinterpret_cast<__half2*>(&u.x));
            float2 hi = __half22float2(*reinterpret_cast<__half2*>(&u.y));
            acc.x += lo.x; acc.y += lo.y; acc.z += hi.x; acc.w += hi.y;
        }
    }
    const float dd = dinv[d];
    const float4 bv = reinterpret_cast<const float4*>(b)[lane];
    float4 o;
    o.x = fmaf(acc.x, dd, bv.x);
    o.y = fmaf(acc.y, dd, bv.y);
    o.z = fmaf(acc.z, dd, bv.z);
    o.w = fmaf(acc.w, dd, bv.w);
    reinterpret_cast<float4*>(A + (size_t)d * 128)[lane] = o;
}

__global__ __launch_bounds__(256) void gather64_kernel(
    const int* __restrict__ csr, const int* __restrict__ rowptr,
    const int* __restrict__ cnt, const float* __restrict__ dinv,
    const __half* __restrict__ H, const float* __restrict__ b,
    float* __restrict__ A, int n0, int n1) {
    int d = n0 + ((blockIdx.x * blockDim.x + threadIdx.x) >> 5);
    int lane = threadIdx.x & 31;
    if (d >= n1) return;
    const int start = rowptr[d];
    const int c = cnt[d];

    float2 acc;
    {
        unsigned u = reinterpret_cast<const unsigned*>(H + (size_t)d * 64)[lane];
        float2 hv = __half22float2(*reinterpret_cast<__half2*>(&u));
        acc.x = hv.x; acc.y = hv.y;
    }

    for (int j0 = 0; j0 < c; j0 += 32) {
        int s = (j0 + lane < c) ? csr[start + j0 + lane] : 0;
        int m = min(32, c - j0);
#pragma unroll 8
        for (int k = 0; k < m; k++) {
            int sk = __shfl_sync(0xffffffffu, s, k);
            unsigned u = reinterpret_cast<const unsigned*>(H + (size_t)sk * 64)[lane];
            float2 v = __half22float2(*reinterpret_cast<__half2*>(&u));
            acc.x += v.x; acc.y += v.y;
        }
    }
    const float dd = dinv[d];
    const float2 bv = reinterpret_cast<const float2*>(b)[lane];
    float2 o;
    o.x = fmaf(acc.x, dd, bv.x);
    o.y = fmaf(acc.y, dd, bv.y);
    reinterpret_cast<float2*>(A + (size_t)d * 64)[lane] = o;
}

// ---------------------------------------------------------------------------
// launch
// ---------------------------------------------------------------------------
extern "C" void kernel_launch(void* const* d_in, const int* in_sizes, int n_in,
                              void* d_out, int out_size) {
    const float* x = (const float*)d_in[0];
    const void* ei = d_in[1];
    const float* W1 = (const float*)d_in[2];
    const float* b1 = (const float*)d_in[3];
    const float* W2 = (const float*)d_in[4];
    const float* b2 = (const float*)d_in[5];
    const float* W3 = (const float*)d_in[6];
    const float* b3 = (const float*)d_in[7];
    float* out = (float*)d_out;

    const int n = in_sizes[0] / 128;
    const int e = in_sizes[1] / 2;

    __half *hA, *hB, *w1h, *w1l, *w2h, *w2l, *w3h, *w3l;
    float *a, *dinv;
    int *cnt, *fill, *rowptr, *incl, *bsum, *csr;
    cudaGetSymbolAddress((void**)&hA, g_hA);
    cudaGetSymbolAddress((void**)&hB, g_hB);
    cudaGetSymbolAddress((void**)&a, g_a);
    cudaGetSymbolAddress((void**)&dinv, g_dinv);
    cudaGetSymbolAddress((void**)&cnt, g_cnt);
    cudaGetSymbolAddress((void**)&fill, g_fill);
    cudaGetSymbolAddress((void**)&rowptr, g_rowptr);
    cudaGetSymbolAddress((void**)&incl, g_incl);
    cudaGetSymbolAddress((void**)&bsum, g_bsum);
    cudaGetSymbolAddress((void**)&csr, g_csr);
    cudaGetSymbolAddress((void**)&w1h, g_w1h);
    cudaGetSymbolAddress((void**)&w1l, g_w1l);
    cudaGetSymbolAddress((void**)&w2h, g_w2h);
    cudaGetSymbolAddress((void**)&w2l, g_w2l);
    cudaGetSymbolAddress((void**)&w3h, g_w3h);
    cudaGetSymbolAddress((void**)&w3l, g_w3l);

    const int T = 256;
    const int nb = (n + SCAN_B - 1) / SCAN_B;

    // node chunks (chunk boundary aligned to 128-row GEMM tiles)
    int nc = ((n / 2) + 127) & ~127;
    if (nc > n) nc = n;
    const int gb0 = nc / 128;                    // gemm blocks chunk0
    const int gb1 = (n - nc + 127) / 128;        // gemm blocks chunk1
    const int ga0 = (nc * 32 + T - 1) / T;       // gather blocks chunk0
    const int ga1 = ((n - nc) * 32 + T - 1) / T; // gather blocks chunk1

    // prefix (main): weight split, probe, degree
    wconv_all_kernel<<<160, 256>>>(W1, W2, W3, w1h, w1l, w2h, w2l, w3h, w3l);
    probe_kernel<<<1, 1024>>>((const unsigned*)ei);
    zero1_kernel<<<(n + T - 1) / T, T>>>(cnt, n);
    count_kernel<<<(e + T - 1) / T, T>>>(ei, cnt, e, n);
    dinv_kernel<<<(n + T - 1) / T, T>>>(cnt, dinv, n);

    // fork: CSR scan/fill on s2, GEMM1 (full) on main
    cudaEventRecord(g_evf, 0);
    cudaStreamWaitEvent(g_s2, g_evf, 0);
    scan_block_kernel<<<nb, SCAN_B, 0, g_s2>>>(cnt, incl, bsum, n);
    scan_bsum_kernel<<<1, 256, 0, g_s2>>>(bsum, nb);
    scan_final_kernel<<<(n + T - 1) / T, T, 0, g_s2>>>(incl, cnt, bsum, rowptr, fill, n);
    fill_csr_kernel<<<(e + T - 1) / T, T, 0, g_s2>>>(ei, fill, csr, e, n);
    cudaEventRecord(g_evcsr, g_s2);

    gemm_tc_kernel<128, false><<<gb0 + gb1, 256>>>(x, w1h, w1l, dinv, hA, n, 0);
    cudaStreamWaitEvent(0, g_evcsr, 0);

    // layer 1 gather (hA -> A), chunked; GEMM2 chunk0 overlaps gather chunk1
    gather128_kernel<<<ga0, T>>>(csr, rowptr, cnt, dinv, hA, b1, a, 0, nc);
    cudaEventRecord(g_ev1, 0);
    if (ga1) gather128_kernel<<<ga1, T>>>(csr, rowptr, cnt, dinv, hA, b1, a, nc, n);

    cudaStreamWaitEvent(g_s2, g_ev1, 0);
    gemm_tc_kernel<128, true><<<gb0, 256, 0, g_s2>>>(a, w2h, w2l, dinv, hB, n, 0);
    cudaEventRecord(g_ev2, g_s2);
    if (gb1) gemm_tc_kernel<128, true><<<gb1, 256>>>(a, w2h, w2l, dinv, hB, n, nc);
    cudaStreamWaitEvent(0, g_ev2, 0);

    // layer 2 gather (hB -> A); GEMM3 chunk0 overlaps gather chunk1
    gather128_kernel<<<ga0, T>>>(csr, rowptr, cnt, dinv, hB, b2, a, 0, nc);
    cudaEventRecord(g_ev3, 0);
    if (ga1) gather128_kernel<<<ga1, T>>>(csr, rowptr, cnt, dinv, hB, b2, a, nc, n);

    cudaStreamWaitEvent(g_s2, g_ev3, 0);
    gemm_tc_kernel<64, true><<<gb0, 256, 0, g_s2>>>(a, w3h, w3l, dinv, hA, n, 0);
    cudaEventRecord(g_ev4, g_s2);
    if (gb1) gemm_tc_kernel<64, true><<<gb1, 256>>>(a, w3h, w3l, dinv, hA, n, nc);
    cudaStreamWaitEvent(0, g_ev4, 0);

    // layer 3 gather (hA -> out)
    gather64_kernel<<<(n * 32 + T - 1) / T, T>>>(csr, rowptr, cnt, dinv, hA, b3,
                                                 out, 0, n);
}

// round 14
// speedup vs baseline: 1.0655x; 1.0655x over previous
#include <cuda_runtime.h>
#include <cuda_fp16.h>
#include <cstdint>

// ---------------------------------------------------------------------------
// GCN 3-layer: CSR-gather over dinv-prescaled fp16 rows + fp16 HMMA GEMM
// (x fp16, W hi/lo 2-split -> 2 MMA per k16 step), CSR-build || GEMM1 overlap.
// out = GCNConv3(relu(GCNConv2(relu(GCNConv1(x)))))
// GCNConv: out = D^-1/2 (A+I) D^-1/2 (x @ W^T) + b
// Identity: A[d] = b + dinv[d]*( H'[d] + sum_e H'[src] ), H' = dinv*H (fp16)
// ---------------------------------------------------------------------------

#define MAXN 100000
#define MAXE 1600000
#define SCAN_B 1024

__device__ __align__(16) __half g_h16[MAXN * 128];  // dinv-prescaled GEMM out
__device__ __align__(16) float g_a[MAXN * 128];     // gather accumulator (fp32)
__device__ float g_dinv[MAXN];
__device__ int g_cnt[MAXN];
__device__ int g_fill[MAXN];
__device__ int g_rowptr[MAXN];
__device__ int g_incl[MAXN];
__device__ int g_bsum[256];
__device__ int g_csr[MAXE];
__device__ int g_is64;

__device__ __align__(16) __half g_w1h[128 * 128], g_w1l[128 * 128];
__device__ __align__(16) __half g_w2h[128 * 128], g_w2l[128 * 128];
__device__ __align__(16) __half g_w3h[64 * 128],  g_w3l[64 * 128];

static cudaStream_t g_s2;
static cudaEvent_t g_ev_fork, g_ev_join;
static bool g_stream_init = []() {
    cudaStreamCreateWithFlags(&g_s2, cudaStreamNonBlocking);
    cudaEventCreateWithFlags(&g_ev_fork, cudaEventDisableTiming);
    cudaEventCreateWithFlags(&g_ev_join, cudaEventDisableTiming);
    return true;
}();

// ---------------------------------------------------------------------------
// helpers
// ---------------------------------------------------------------------------
__device__ __forceinline__ void split_h(float v, __half& h, __half& l) {
    h = __float2half_rn(v);
    l = __float2half_rn(v - __half2float(h));
}

__device__ __forceinline__ void mma_f16(float* c, const unsigned* a,
                                        const unsigned* b) {
    asm("mma.sync.aligned.m16n8k16.row.col.f32.f16.f16.f32 "
        "{%0,%1,%2,%3},{%4,%5,%6,%7},{%8,%9},{%0,%1,%2,%3};"
        : "+f"(c[0]), "+f"(c[1]), "+f"(c[2]), "+f"(c[3])
        : "r"(a[0]), "r"(a[1]), "r"(a[2]), "r"(a[3]), "r"(b[0]), "r"(b[1]));
}

// fused weight pre-split (one launch for all three W)
__global__ void wconv_all_kernel(const float* __restrict__ W1,
                                 const float* __restrict__ W2,
                                 const float* __restrict__ W3,
                                 __half* __restrict__ w1h, __half* __restrict__ w1l,
                                 __half* __restrict__ w2h, __half* __restrict__ w2l,
                                 __half* __restrict__ w3h, __half* __restrict__ w3l) {
    int i = blockIdx.x * blockDim.x + threadIdx.x;
    __half h, l;
    if (i < 16384) {
        split_h(W1[i], h, l); w1h[i] = h; w1l[i] = l;
    } else if (i < 32768) {
        int j = i - 16384;
        split_h(W2[j], h, l); w2h[j] = h; w2l[j] = l;
    } else if (i < 40960) {
        int j = i - 32768;
        split_h(W3[j], h, l); w3h[j] = h; w3l[j] = l;
    }
}

// fused dtype probe: one block, thread 0 inits, all threads sample
__global__ void probe_kernel(const unsigned* __restrict__ ei) {
    if (threadIdx.x == 0) g_is64 = 1;
    __syncthreads();
    if (ei[2 * threadIdx.x + 1] != 0) atomicAnd(&g_is64, 0);
}

__device__ __forceinline__ void load_edge(const void* ei, int e, int g, int is64,
                                          int& s, int& d) {
    if (is64) {
        const long long* p = (const long long*)ei;
        s = (int)p[g];
        d = (int)p[e + g];
    } else {
        const int* p = (const int*)ei;
        s = p[g];
        d = p[e + g];
    }
}

// ---------------------------------------------------------------------------
// CSR build
// ---------------------------------------------------------------------------
__global__ void zero1_kernel(int* __restrict__ a, int n) {
    int i = blockIdx.x * blockDim.x + threadIdx.x;
    if (i < n) a[i] = 0;
}

// dst-only read (half the edge bytes)
__global__ void count_kernel(const void* __restrict__ ei, int* __restrict__ cnt,
                             int e, int n) {
    int i = blockIdx.x * blockDim.x + threadIdx.x;
    if (i >= e) return;
    int d;
    if (g_is64) d = (int)((const long long*)ei)[e + i];
    else        d = ((const int*)ei)[e + i];
    if ((unsigned)d < (unsigned)n) atomicAdd(&cnt[d], 1);
}

__global__ void dinv_kernel(const int* __restrict__ cnt, float* __restrict__ dinv,
                            int n) {
    int i = blockIdx.x * blockDim.x + threadIdx.x;
    if (i < n) dinv[i] = rsqrtf((float)cnt[i] + 1.0f);
}

__global__ __launch_bounds__(SCAN_B) void scan_block_kernel(
    const int* __restrict__ cnt, int* __restrict__ incl, int* __restrict__ bsum,
    int n) {
    __shared__ int sm[SCAN_B];
    int i = blockIdx.x * SCAN_B + threadIdx.x;
    int v = (i < n) ? cnt[i] : 0;
    sm[threadIdx.x] = v;
    __syncthreads();
#pragma unroll
    for (int off = 1; off < SCAN_B; off <<= 1) {
        int t = (threadIdx.x >= off) ? sm[threadIdx.x - off] : 0;
        __syncthreads();
        sm[threadIdx.x] += t;
        __syncthreads();
    }
    if (i < n) incl[i] = sm[threadIdx.x];
    if (threadIdx.x == SCAN_B - 1) bsum[blockIdx.x] = sm[SCAN_B - 1];
}

__global__ __launch_bounds__(256) void scan_bsum_kernel(int* __restrict__ bsum,
                                                        int nb) {
    __shared__ int sm[256];
    int v = (threadIdx.x < nb) ? bsum[threadIdx.x] : 0;
    sm[threadIdx.x] = v;
    __syncthreads();
#pragma unroll
    for (int off = 1; off < 256; off <<= 1) {
        int t = (threadIdx.x >= off) ? sm[threadIdx.x - off] : 0;
        __syncthreads();
        sm[threadIdx.x] += t;
        __syncthreads();
    }
    if (threadIdx.x < nb) bsum[threadIdx.x] = sm[threadIdx.x] - v;
}

__global__ void scan_final_kernel(const int* __restrict__ incl,
                                  const int* __restrict__ cnt,
                                  const int* __restrict__ bsum,
                                  int* __restrict__ rowptr,
                                  int* __restrict__ fill, int n) {
    int i = blockIdx.x * blockDim.x + threadIdx.x;
    if (i < n) {
        int rp = incl[i] - cnt[i] + bsum[i / SCAN_B];
        rowptr[i] = rp;
        fill[i] = rp;
    }
}

__global__ void fill_csr_kernel(const void* __restrict__ ei,
                                int* __restrict__ fill, int* __restrict__ csr,
                                int e, int n) {
    int i = blockIdx.x * blockDim.x + threadIdx.x;
    if (i >= e) return;
    int s, d;
    load_edge(ei, e, i, g_is64, s, d);
    if ((unsigned)s >= (unsigned)n || (unsigned)d >= (unsigned)n) return;
    int pos = atomicAdd(&fill[d], 1);
    csr[pos] = s;
}

// ---------------------------------------------------------------------------
// fp16 HMMA GEMM (x fp16; W hi/lo; 2 MMA per k16 step):
// H16[r,:] = fp16( dinv[r] * (act(X[r,:]) @ W^T) )
// ---------------------------------------------------------------------------
template <int COLS, bool RELU>
__global__ __launch_bounds__(256) void gemm_tc_kernel(
    const float* __restrict__ X, const __half* __restrict__ Wh,
    const __half* __restrict__ Wl, const float* __restrict__ dinv,
    __half* __restrict__ H, int n) {
    __shared__ __half xs[128][40];
    __shared__ __half ws_h[COLS][40], ws_l[COLS][40];

    constexpr int WM = (COLS == 128) ? 2 : 1;
    const int t = threadIdx.x;
    const int wid = t >> 5;
    const int lane = t & 31;
    const int gid = lane >> 2;
    const int tig = lane & 3;
    const int row0 = blockIdx.x * 128;

    int wm0, wn0;
    if (COLS == 128) { wm0 = (wid >> 1) * 32; wn0 = (wid & 1) * 64; }
    else             { wm0 = wid * 16;        wn0 = 0; }

    float acc[WM][8][4];
#pragma unroll
    for (int mt = 0; mt < WM; mt++)
#pragma unroll
        for (int nt = 0; nt < 8; nt++)
#pragma unroll
            for (int i = 0; i < 4; i++) acc[mt][nt][i] = 0.0f;

    for (int kb = 0; kb < 128; kb += 32) {
        for (int idx = t; idx < 128 * 32; idx += 256) {
            int r = idx >> 5, k = idx & 31;
            int row = row0 + r;
            float v = 0.0f;
            if (row < n) {
                v = X[row * 128 + kb + k];
                if (RELU) v = fmaxf(v, 0.0f);
            }
            xs[r][k] = __float2half_rn(v);
        }
        for (int idx = t; idx < COLS * 32; idx += 256) {
            int c = idx >> 5, k = idx & 31;
            ws_h[c][k] = Wh[c * 128 + kb + k];
            ws_l[c][k] = Wl[c * 128 + kb + k];
        }
        __syncthreads();

#pragma unroll
        for (int ks = 0; ks < 2; ks++) {
            const int k0 = ks * 16;
            unsigned ax[WM][4];
#pragma unroll
            for (int mt = 0; mt < WM; mt++) {
                int r = wm0 + mt * 16 + gid;
                ax[mt][0] = *reinterpret_cast<const unsigned*>(&xs[r][k0 + tig * 2]);
                ax[mt][1] = *reinterpret_cast<const unsigned*>(&xs[r + 8][k0 + tig * 2]);
                ax[mt][2] = *reinterpret_cast<const unsigned*>(&xs[r][k0 + tig * 2 + 8]);
                ax[mt][3] = *reinterpret_cast<const unsigned*>(&xs[r + 8][k0 + tig * 2 + 8]);
            }
#pragma unroll
            for (int nt = 0; nt < 8; nt++) {
                int c = wn0 + nt * 8 + gid;
                unsigned bh[2], bl[2];
                bh[0] = *reinterpret_cast<const unsigned*>(&ws_h[c][k0 + tig * 2]);
                bh[1] = *reinterpret_cast<const unsigned*>(&ws_h[c][k0 + tig * 2 + 8]);
                bl[0] = *reinterpret_cast<const unsigned*>(&ws_l[c][k0 + tig * 2]);
                bl[1] = *reinterpret_cast<const unsigned*>(&ws_l[c][k0 + tig * 2 + 8]);
#pragma unroll
                for (int mt = 0; mt < WM; mt++) {
                    mma_f16(acc[mt][nt], ax[mt], bl);
                    mma_f16(acc[mt][nt], ax[mt], bh);
                }
            }
        }
        __syncthreads();
    }

#pragma unroll
    for (int mt = 0; mt < WM; mt++) {
        int r = row0 + wm0 + mt * 16 + gid;
        float d0 = (r < n) ? dinv[r] : 0.0f;
        float d1 = (r + 8 < n) ? dinv[r + 8] : 0.0f;
#pragma unroll
        for (int nt = 0; nt < 8; nt++) {
            int c = wn0 + nt * 8 + tig * 2;
            if (r < n)
                *reinterpret_cast<__half2*>(H + (size_t)r * COLS + c) =
                    __floats2half2_rn(acc[mt][nt][0] * d0, acc[mt][nt][1] * d0);
            if (r + 8 < n)
                *reinterpret_cast<__half2*>(H + (size_t)(r + 8) * COLS + c) =
                    __floats2half2_rn(acc[mt][nt][2] * d1, acc[mt][nt][3] * d1);
        }
    }
}

// ---------------------------------------------------------------------------
// gather (one warp per node), prescaled fp16 rows:
// A[d] = b + dinv[d]*( H'[d] + sum_e H'[src] )
// ---------------------------------------------------------------------------
__global__ __launch_bounds__(256) void gather128_kernel(
    const int* __restrict__ csr, const int* __restrict__ rowptr,
    const int* __restrict__ cnt, const float* __restrict__ dinv,
    const __half* __restrict__ H, const float* __restrict__ b,
    float* __restrict__ A, int n) {
    int d = (blockIdx.x * blockDim.x + threadIdx.x) >> 5;
    int lane = threadIdx.x & 31;
    if (d >= n) return;
    const int start = rowptr[d];
    const int c = cnt[d];

    float4 acc;
    {
        uint2 u = reinterpret_cast<const uint2*>(H + (size_t)d * 128)[lane];
        float2 lo = __half22float2(*reinterpret_cast<__half2*>(&u.x));
        float2 hi = __half22float2(*reinterpret_cast<__half2*>(&u.y));
        acc.x = lo.x; acc.y = lo.y; acc.z = hi.x; acc.w = hi.y;
    }

    for (int j0 = 0; j0 < c; j0 += 32) {
        int s = (j0 + lane < c) ? csr[start + j0 + lane] : 0;
        int m = min(32, c - j0);
#pragma unroll 8
        for (int k = 0; k < m; k++) {
            int sk = __shfl_sync(0xffffffffu, s, k);
            uint2 u = reinterpret_cast<const uint2*>(H + (size_t)sk * 128)[lane];
            float2 lo = __half22float2(*reinterpret_cast<__half2*>(&u.x));
            float2 hi = __half22float2(*reinterpret_cast<__half2*>(&u.y));
            acc.x += lo.x; acc.y += lo.y; acc.z += hi.x; acc.w += hi.y;
        }
    }
    const float dd = dinv[d];
    const float4 bv = reinterpret_cast<const float4*>(b)[lane];
    float4 o;
    o.x = fmaf(acc.x, dd, bv.x);
    o.y = fmaf(acc.y, dd, bv.y);
    o.z = fmaf(acc.z, dd, bv.z);
    o.w = fmaf(acc.w, dd, bv.w);
    reinterpret_cast<float4*>(A + (size_t)d * 128)[lane] = o;
}

__global__ __launch_bounds__(256) void gather64_kernel(
    const int* __restrict__ csr, const int* __restrict__ rowptr,
    const int* __restrict__ cnt, const float* __restrict__ dinv,
    const __half* __restrict__ H, const float* __restrict__ b,
    float* __restrict__ A, int n) {
    int d = (blockIdx.x * blockDim.x + threadIdx.x) >> 5;
    int lane = threadIdx.x & 31;
    if (d >= n) return;
    const int start = rowptr[d];
    const int c = cnt[d];

    float2 acc;
    {
        unsigned u = reinterpret_cast<const unsigned*>(H + (size_t)d * 64)[lane];
        float2 hv = __half22float2(*reinterpret_cast<__half2*>(&u));
        acc.x = hv.x; acc.y = hv.y;
    }

    for (int j0 = 0; j0 < c; j0 += 32) {
        int s = (j0 + lane < c) ? csr[start + j0 + lane] : 0;
        int m = min(32, c - j0);
#pragma unroll 8
        for (int k = 0; k < m; k++) {
            int sk = __shfl_sync(0xffffffffu, s, k);
            unsigned u = reinterpret_cast<const unsigned*>(H + (size_t)sk * 64)[lane];
            float2 v = __half22float2(*reinterpret_cast<__half2*>(&u));
            acc.x += v.x; acc.y += v.y;
        }
    }
    const float dd = dinv[d];
    const float2 bv = reinterpret_cast<const float2*>(b)[lane];
    float2 o;
    o.x = fmaf(acc.x, dd, bv.x);
    o.y = fmaf(acc.y, dd, bv.y);
    reinterpret_cast<float2*>(A + (size_t)d * 64)[lane] = o;
}

// ---------------------------------------------------------------------------
// launch  (R12 schedule: CSR scan/fill || GEMM1 only)
// ---------------------------------------------------------------------------
extern "C" void kernel_launch(void* const* d_in, const int* in_sizes, int n_in,
                              void* d_out, int out_size) {
    const float* x = (const float*)d_in[0];
    const void* ei = d_in[1];
    const float* W1 = (const float*)d_in[2];
    const float* b1 = (const float*)d_in[3];
    const float* W2 = (const float*)d_in[4];
    const float* b2 = (const float*)d_in[5];
    const float* W3 = (const float*)d_in[6];
    const float* b3 = (const float*)d_in[7];
    float* out = (float*)d_out;

    const int n = in_sizes[0] / 128;
    const int e = in_sizes[1] / 2;

    __half *h16, *w1h, *w1l, *w2h, *w2l, *w3h, *w3l;
    float *a, *dinv;
    int *cnt, *fill, *rowptr, *incl, *bsum, *csr;
    cudaGetSymbolAddress((void**)&h16, g_h16);
    cudaGetSymbolAddress((void**)&a, g_a);
    cudaGetSymbolAddress((void**)&dinv, g_dinv);
    cudaGetSymbolAddress((void**)&cnt, g_cnt);
    cudaGetSymbolAddress((void**)&fill, g_fill);
    cudaGetSymbolAddress((void**)&rowptr, g_rowptr);
    cudaGetSymbolAddress((void**)&incl, g_incl);
    cudaGetSymbolAddress((void**)&bsum, g_bsum);
    cudaGetSymbolAddress((void**)&csr, g_csr);
    cudaGetSymbolAddress((void**)&w1h, g_w1h);
    cudaGetSymbolAddress((void**)&w1l, g_w1l);
    cudaGetSymbolAddress((void**)&w2h, g_w2h);
    cudaGetSymbolAddress((void**)&w2l, g_w2l);
    cudaGetSymbolAddress((void**)&w3h, g_w3h);
    cudaGetSymbolAddress((void**)&w3l, g_w3l);

    const int T = 256;
    const int nb = (n + SCAN_B - 1) / SCAN_B;
    const int gemm_blocks = (n + 127) / 128;
    const int gather_blocks = (n * 32 + T - 1) / T;

    // prefix: weight split, probe, degree
    wconv_all_kernel<<<160, 256>>>(W1, W2, W3, w1h, w1l, w2h, w2l, w3h, w3l);
    probe_kernel<<<1, 1024>>>((const unsigned*)ei);
    zero1_kernel<<<(n + T - 1) / T, T>>>(cnt, n);
    count_kernel<<<(e + T - 1) / T, T>>>(ei, cnt, e, n);
    dinv_kernel<<<(n + T - 1) / T, T>>>(cnt, dinv, n);

    // fork: scan+fill on side stream, GEMM1 on main stream
    cudaEventRecord(g_ev_fork, 0);
    cudaStreamWaitEvent(g_s2, g_ev_fork, 0);
    scan_block_kernel<<<nb, SCAN_B, 0, g_s2>>>(cnt, incl, bsum, n);
    scan_bsum_kernel<<<1, 256, 0, g_s2>>>(bsum, nb);
    scan_final_kernel<<<(n + T - 1) / T, T, 0, g_s2>>>(incl, cnt, bsum, rowptr,
                                                       fill, n);
    fill_csr_kernel<<<(e + T - 1) / T, T, 0, g_s2>>>(ei, fill, csr, e, n);
    cudaEventRecord(g_ev_join, g_s2);

    gemm_tc_kernel<128, false><<<gemm_blocks, 256>>>(x, w1h, w1l, dinv, h16, n);
    cudaStreamWaitEvent(0, g_ev_join, 0);

    gather128_kernel<<<gather_blocks, T>>>(csr, rowptr, cnt, dinv, h16, b1, a, n);

    gemm_tc_kernel<128, true><<<gemm_blocks, 256>>>(a, w2h, w2l, dinv, h16, n);
    gather128_kernel<<<gather_blocks, T>>>(csr, rowptr, cnt, dinv, h16, b2, a, n);

    gemm_tc_kernel<64, true><<<gemm_blocks, 256>>>(a, w3h, w3l, dinv, h16, n);
    gather64_kernel<<<gather_blocks, T>>>(csr, rowptr, cnt, dinv, h16, b3, out, n);
}

// round 15
// speedup vs baseline: 1.1930x; 1.1197x over previous
#include <cuda_runtime.h>
#include <cuda_fp16.h>
#include <cstdint>

// ---------------------------------------------------------------------------
// GCN 3-layer: CSR-gather over fp16 rows + fp16 HMMA GEMM (W hi/lo).
// Layer 1: GEMM writes RAW H (no dinv) so it fully overlaps the degree/CSR
//          pipeline; gather1 applies dinv[s]*dinv[d] per edge.
// Layers 2/3: dinv prescaled in GEMM epilogue; gather is plain adds.
// Inter-layer activations A stored fp16 (GEMM2/3 read fp16 directly).
// ---------------------------------------------------------------------------

#define MAXN 100000
#define MAXE 1600000
#define SCAN_B 1024

__device__ __align__(16) __half g_h16[MAXN * 128];  // GEMM out
__device__ __align__(16) __half g_a16[MAXN * 128];  // gather out (fp16)
__device__ float g_dinv[MAXN];
__device__ int g_cnt[MAXN];
__device__ int g_fill[MAXN];
__device__ int g_rowptr[MAXN];
__device__ int g_incl[MAXN];
__device__ int g_bsum[256];
__device__ int g_csr[MAXE];
__device__ int g_is64;

__device__ __align__(16) __half g_w1h[128 * 128], g_w1l[128 * 128];
__device__ __align__(16) __half g_w2h[128 * 128], g_w2l[128 * 128];
__device__ __align__(16) __half g_w3h[64 * 128],  g_w3l[64 * 128];

static cudaStream_t g_s2;
static cudaEvent_t g_ev_fork, g_ev_join;
static bool g_stream_init = []() {
    cudaStreamCreateWithFlags(&g_s2, cudaStreamNonBlocking);
    cudaEventCreateWithFlags(&g_ev_fork, cudaEventDisableTiming);
    cudaEventCreateWithFlags(&g_ev_join, cudaEventDisableTiming);
    return true;
}();

// ---------------------------------------------------------------------------
// helpers
// ---------------------------------------------------------------------------
__device__ __forceinline__ void split_h(float v, __half& h, __half& l) {
    h = __float2half_rn(v);
    l = __float2half_rn(v - __half2float(h));
}

__device__ __forceinline__ void mma_f16(float* c, const unsigned* a,
                                        const unsigned* b) {
    asm("mma.sync.aligned.m16n8k16.row.col.f32.f16.f16.f32 "
        "{%0,%1,%2,%3},{%4,%5,%6,%7},{%8,%9},{%0,%1,%2,%3};"
        : "+f"(c[0]), "+f"(c[1]), "+f"(c[2]), "+f"(c[3])
        : "r"(a[0]), "r"(a[1]), "r"(a[2]), "r"(a[3]), "r"(b[0]), "r"(b[1]));
}

__global__ void wconv_all_kernel(const float* __restrict__ W1,
                                 const float* __restrict__ W2,
                                 const float* __restrict__ W3,
                                 __half* __restrict__ w1h, __half* __restrict__ w1l,
                                 __half* __restrict__ w2h, __half* __restrict__ w2l,
                                 __half* __restrict__ w3h, __half* __restrict__ w3l) {
    int i = blockIdx.x * blockDim.x + threadIdx.x;
    __half h, l;
    if (i < 16384) {
        split_h(W1[i], h, l); w1h[i] = h; w1l[i] = l;
    } else if (i < 32768) {
        int j = i - 16384;
        split_h(W2[j], h, l); w2h[j] = h; w2l[j] = l;
    } else if (i < 40960) {
        int j = i - 32768;
        split_h(W3[j], h, l); w3h[j] = h; w3l[j] = l;
    }
}

__global__ void probe_kernel(const unsigned* __restrict__ ei) {
    if (threadIdx.x == 0) g_is64 = 1;
    __syncthreads();
    if (ei[2 * threadIdx.x + 1] != 0) atomicAnd(&g_is64, 0);
}

__device__ __forceinline__ void load_edge(const void* ei, int e, int g, int is64,
                                          int& s, int& d) {
    if (is64) {
        const long long* p = (const long long*)ei;
        s = (int)p[g];
        d = (int)p[e + g];
    } else {
        const int* p = (const int*)ei;
        s = p[g];
        d = p[e + g];
    }
}

// ---------------------------------------------------------------------------
// CSR build
// ---------------------------------------------------------------------------
__global__ void zero1_kernel(int* __restrict__ a, int n) {
    int i = blockIdx.x * blockDim.x + threadIdx.x;
    if (i < n) a[i] = 0;
}

__global__ void count_kernel(const void* __restrict__ ei, int* __restrict__ cnt,
                             int e, int n) {
    int i = blockIdx.x * blockDim.x + threadIdx.x;
    if (i >= e) return;
    int d;
    if (g_is64) d = (int)((const long long*)ei)[e + i];
    else        d = ((const int*)ei)[e + i];
    if ((unsigned)d < (unsigned)n) atomicAdd(&cnt[d], 1);
}

__global__ void dinv_kernel(const int* __restrict__ cnt, float* __restrict__ dinv,
                            int n) {
    int i = blockIdx.x * blockDim.x + threadIdx.x;
    if (i < n) dinv[i] = rsqrtf((float)cnt[i] + 1.0f);
}

__global__ __launch_bounds__(SCAN_B) void scan_block_kernel(
    const int* __restrict__ cnt, int* __restrict__ incl, int* __restrict__ bsum,
    int n) {
    __shared__ int sm[SCAN_B];
    int i = blockIdx.x * SCAN_B + threadIdx.x;
    int v = (i < n) ? cnt[i] : 0;
    sm[threadIdx.x] = v;
    __syncthreads();
#pragma unroll
    for (int off = 1; off < SCAN_B; off <<= 1) {
        int t = (threadIdx.x >= off) ? sm[threadIdx.x - off] : 0;
        __syncthreads();
        sm[threadIdx.x] += t;
        __syncthreads();
    }
    if (i < n) incl[i] = sm[threadIdx.x];
    if (threadIdx.x == SCAN_B - 1) bsum[blockIdx.x] = sm[SCAN_B - 1];
}

__global__ __launch_bounds__(256) void scan_bsum_kernel(int* __restrict__ bsum,
                                                        int nb) {
    __shared__ int sm[256];
    int v = (threadIdx.x < nb) ? bsum[threadIdx.x] : 0;
    sm[threadIdx.x] = v;
    __syncthreads();
#pragma unroll
    for (int off = 1; off < 256; off <<= 1) {
        int t = (threadIdx.x >= off) ? sm[threadIdx.x - off] : 0;
        __syncthreads();
        sm[threadIdx.x] += t;
        __syncthreads();
    }
    if (threadIdx.x < nb) bsum[threadIdx.x] = sm[threadIdx.x] - v;
}

__global__ void scan_final_kernel(const int* __restrict__ incl,
                                  const int* __restrict__ cnt,
                                  const int* __restrict__ bsum,
                                  int* __restrict__ rowptr,
                                  int* __restrict__ fill, int n) {
    int i = blockIdx.x * blockDim.x + threadIdx.x;
    if (i < n) {
        int rp = incl[i] - cnt[i] + bsum[i / SCAN_B];
        rowptr[i] = rp;
        fill[i] = rp;
    }
}

__global__ void fill_csr_kernel(const void* __restrict__ ei,
                                int* __restrict__ fill, int* __restrict__ csr,
                                int e, int n) {
    int i = blockIdx.x * blockDim.x + threadIdx.x;
    if (i >= e) return;
    int s, d;
    load_edge(ei, e, i, g_is64, s, d);
    if ((unsigned)s >= (unsigned)n || (unsigned)d >= (unsigned)n) return;
    int pos = atomicAdd(&fill[d], 1);
    csr[pos] = s;
}

// ---------------------------------------------------------------------------
// fp16 HMMA GEMM. HALFIN: X is __half (direct copy stage, relu via hmax2);
// else X is fp32 (cvt in stage). PRESCALE: multiply rows by dinv in epilogue.
// ---------------------------------------------------------------------------
template <int COLS, bool RELU, bool PRESCALE, bool HALFIN>
__global__ __launch_bounds__(256) void gemm_tc_kernel(
    const void* __restrict__ Xv, const __half* __restrict__ Wh,
    const __half* __restrict__ Wl, const float* __restrict__ dinv,
    __half* __restrict__ H, int n) {
    __shared__ __half xs[128][40];
    __shared__ __half ws_h[COLS][40], ws_l[COLS][40];

    constexpr int WM = (COLS == 128) ? 2 : 1;
    const int t = threadIdx.x;
    const int wid = t >> 5;
    const int lane = t & 31;
    const int gid = lane >> 2;
    const int tig = lane & 3;
    const int row0 = blockIdx.x * 128;

    int wm0, wn0;
    if (COLS == 128) { wm0 = (wid >> 1) * 32; wn0 = (wid & 1) * 64; }
    else             { wm0 = wid * 16;        wn0 = 0; }

    float acc[WM][8][4];
#pragma unroll
    for (int mt = 0; mt < WM; mt++)
#pragma unroll
        for (int nt = 0; nt < 8; nt++)
#pragma unroll
            for (int i = 0; i < 4; i++) acc[mt][nt][i] = 0.0f;

    for (int kb = 0; kb < 128; kb += 32) {
        if (HALFIN) {
            const unsigned* X2 = (const unsigned*)Xv;  // half2 view, 64/row
            for (int idx = t; idx < 128 * 16; idx += 256) {
                int r = idx >> 4, kk = idx & 15;
                int row = row0 + r;
                unsigned u = 0;
                if (row < n) {
                    u = X2[row * 64 + (kb >> 1) + kk];
                    if (RELU) {
                        __half2 z = __float2half2_rn(0.0f);
                        __half2 v = *reinterpret_cast<__half2*>(&u);
                        v = __hmax2(v, z);
                        u = *reinterpret_cast<unsigned*>(&v);
                    }
                }
                *reinterpret_cast<unsigned*>(&xs[r][2 * kk]) = u;
            }
        } else {
            const float* X = (const float*)Xv;
            for (int idx = t; idx < 128 * 32; idx += 256) {
                int r = idx >> 5, k = idx & 31;
                int row = row0 + r;
                float v = 0.0f;
                if (row < n) {
                    v = X[row * 128 + kb + k];
                    if (RELU) v = fmaxf(v, 0.0f);
                }
                xs[r][k] = __float2half_rn(v);
            }
        }
        for (int idx = t; idx < COLS * 32; idx += 256) {
            int c = idx >> 5, k = idx & 31;
            ws_h[c][k] = Wh[c * 128 + kb + k];
            ws_l[c][k] = Wl[c * 128 + kb + k];
        }
        __syncthreads();

#pragma unroll
        for (int ks = 0; ks < 2; ks++) {
            const int k0 = ks * 16;
            unsigned ax[WM][4];
#pragma unroll
            for (int mt = 0; mt < WM; mt++) {
                int r = wm0 + mt * 16 + gid;
                ax[mt][0] = *reinterpret_cast<const unsigned*>(&xs[r][k0 + tig * 2]);
                ax[mt][1] = *reinterpret_cast<const unsigned*>(&xs[r + 8][k0 + tig * 2]);
                ax[mt][2] = *reinterpret_cast<const unsigned*>(&xs[r][k0 + tig * 2 + 8]);
                ax[mt][3] = *reinterpret_cast<const unsigned*>(&xs[r + 8][k0 + tig * 2 + 8]);
            }
#pragma unroll
            for (int nt = 0; nt < 8; nt++) {
                int c = wn0 + nt * 8 + gid;
                unsigned bh[2], bl[2];
                bh[0] = *reinterpret_cast<const unsigned*>(&ws_h[c][k0 + tig * 2]);
                bh[1] = *reinterpret_cast<const unsigned*>(&ws_h[c][k0 + tig * 2 + 8]);
                bl[0] = *reinterpret_cast<const unsigned*>(&ws_l[c][k0 + tig * 2]);
                bl[1] = *reinterpret_cast<const unsigned*>(&ws_l[c][k0 + tig * 2 + 8]);
#pragma unroll
                for (int mt = 0; mt < WM; mt++) {
                    mma_f16(acc[mt][nt], ax[mt], bl);
                    mma_f16(acc[mt][nt], ax[mt], bh);
                }
            }
        }
        __syncthreads();
    }

#pragma unroll
    for (int mt = 0; mt < WM; mt++) {
        int r = row0 + wm0 + mt * 16 + gid;
        float d0 = 1.0f, d1 = 1.0f;
        if (PRESCALE) {
            d0 = (r < n) ? dinv[r] : 0.0f;
            d1 = (r + 8 < n) ? dinv[r + 8] : 0.0f;
        }
#pragma unroll
        for (int nt = 0; nt < 8; nt++) {
            int c = wn0 + nt * 8 + tig * 2;
            if (r < n)
                *reinterpret_cast<__half2*>(H + (size_t)r * COLS + c) =
                    __floats2half2_rn(acc[mt][nt][0] * d0, acc[mt][nt][1] * d0);
            if (r + 8 < n)
                *reinterpret_cast<__half2*>(H + (size_t)(r + 8) * COLS + c) =
                    __floats2half2_rn(acc[mt][nt][2] * d1, acc[mt][nt][3] * d1);
        }
    }
}

// ---------------------------------------------------------------------------
// gather1 (weighted; H raw): A16[d] = fp16( b + dd^2*H[d] + sum w_e*H[s] ),
// w_e = dinv[s]*dd
// ---------------------------------------------------------------------------
__global__ __launch_bounds__(256) void gather128w_kernel(
    const int* __restrict__ csr, const int* __restrict__ rowptr,
    const int* __restrict__ cnt, const float* __restrict__ dinv,
    const __half* __restrict__ H, const float* __restrict__ b,
    __half* __restrict__ A, int n) {
    int d = (blockIdx.x * blockDim.x + threadIdx.x) >> 5;
    int lane = threadIdx.x & 31;
    if (d >= n) return;
    const int start = rowptr[d];
    const int c = cnt[d];
    const float dd = dinv[d];

    float4 acc;
    {
        float w0 = dd * dd;
        uint2 u = reinterpret_cast<const uint2*>(H + (size_t)d * 128)[lane];
        float2 lo = __half22float2(*reinterpret_cast<__half2*>(&u.x));
        float2 hi = __half22float2(*reinterpret_cast<__half2*>(&u.y));
        acc.x = lo.x * w0; acc.y = lo.y * w0; acc.z = hi.x * w0; acc.w = hi.y * w0;
    }

    for (int j0 = 0; j0 < c; j0 += 32) {
        int valid = j0 + lane < c;
        int s = valid ? csr[start + j0 + lane] : 0;
        float ws = valid ? dinv[s] * dd : 0.0f;
        int m = min(32, c - j0);
#pragma unroll 8
        for (int k = 0; k < m; k++) {
            int sk = __shfl_sync(0xffffffffu, s, k);
            float wk = __shfl_sync(0xffffffffu, ws, k);
            uint2 u = reinterpret_cast<const uint2*>(H + (size_t)sk * 128)[lane];
            float2 lo = __half22float2(*reinterpret_cast<__half2*>(&u.x));
            float2 hi = __half22float2(*reinterpret_cast<__half2*>(&u.y));
            acc.x = fmaf(lo.x, wk, acc.x);
            acc.y = fmaf(lo.y, wk, acc.y);
            acc.z = fmaf(hi.x, wk, acc.z);
            acc.w = fmaf(hi.y, wk, acc.w);
        }
    }
    const float4 bv = reinterpret_cast<const float4*>(b)[lane];
    uint2 o;
    __half2 o0 = __floats2half2_rn(acc.x + bv.x, acc.y + bv.y);
    __half2 o1 = __floats2half2_rn(acc.z + bv.z, acc.w + bv.w);
    o.x = *reinterpret_cast<unsigned*>(&o0);
    o.y = *reinterpret_cast<unsigned*>(&o1);
    reinterpret_cast<uint2*>(A + (size_t)d * 128)[lane] = o;
}

// gather (prescaled H): A16[d] = fp16( b + dd*( H'[d] + sum H'[s] ) )
__global__ __launch_bounds__(256) void gather128_kernel(
    const int* __restrict__ csr, const int* __restrict__ rowptr,
    const int* __restrict__ cnt, const float* __restrict__ dinv,
    const __half* __restrict__ H, const float* __restrict__ b,
    __half* __restrict__ A, int n) {
    int d = (blockIdx.x * blockDim.x + threadIdx.x) >> 5;
    int lane = threadIdx.x & 31;
    if (d >= n) return;
    const int start = rowptr[d];
    const int c = cnt[d];

    float4 acc;
    {
        uint2 u = reinterpret_cast<const uint2*>(H + (size_t)d * 128)[lane];
        float2 lo = __half22float2(*reinterpret_cast<__half2*>(&u.x));
        float2 hi = __half22float2(*reinterpret_cast<__half2*>(&u.y));
        acc.x = lo.x; acc.y = lo.y; acc.z = hi.x; acc.w = hi.y;
    }

    for (int j0 = 0; j0 < c; j0 += 32) {
        int s = (j0 + lane < c) ? csr[start + j0 + lane] : 0;
        int m = min(32, c - j0);
#pragma unroll 8
        for (int k = 0; k < m; k++) {
            int sk = __shfl_sync(0xffffffffu, s, k);
            uint2 u = reinterpret_cast<const uint2*>(H + (size_t)sk * 128)[lane];
            float2 lo = __half22float2(*reinterpret_cast<__half2*>(&u.x));
            float2 hi = __half22float2(*reinterpret_cast<__half2*>(&u.y));
            acc.x += lo.x; acc.y += lo.y; acc.z += hi.x; acc.w += hi.y;
        }
    }
    const float dd = dinv[d];
    const float4 bv = reinterpret_cast<const float4*>(b)[lane];
    uint2 o;
    __half2 o0 = __floats2half2_rn(fmaf(acc.x, dd, bv.x), fmaf(acc.y, dd, bv.y));
    __half2 o1 = __floats2half2_rn(fmaf(acc.z, dd, bv.z), fmaf(acc.w, dd, bv.w));
    o.x = *reinterpret_cast<unsigned*>(&o0);
    o.y = *reinterpret_cast<unsigned*>(&o1);
    reinterpret_cast<uint2*>(A + (size_t)d * 128)[lane] = o;
}

// final gather: fp32 out
__global__ __launch_bounds__(256) void gather64_kernel(
    const int* __restrict__ csr, const int* __restrict__ rowptr,
    const int* __restrict__ cnt, const float* __restrict__ dinv,
    const __half* __restrict__ H, const float* __restrict__ b,
    float* __restrict__ A, int n) {
    int d = (blockIdx.x * blockDim.x + threadIdx.x) >> 5;
    int lane = threadIdx.x & 31;
    if (d >= n) return;
    const int start = rowptr[d];
    const int c = cnt[d];

    float2 acc;
    {
        unsigned u = reinterpret_cast<const unsigned*>(H + (size_t)d * 64)[lane];
        float2 hv = __half22float2(*reinterpret_cast<__half2*>(&u));
        acc.x = hv.x; acc.y = hv.y;
    }

    for (int j0 = 0; j0 < c; j0 += 32) {
        int s = (j0 + lane < c) ? csr[start + j0 + lane] : 0;
        int m = min(32, c - j0);
#pragma unroll 8
        for (int k = 0; k < m; k++) {
            int sk = __shfl_sync(0xffffffffu, s, k);
            unsigned u = reinterpret_cast<const unsigned*>(H + (size_t)sk * 64)[lane];
            float2 v = __half22float2(*reinterpret_cast<__half2*>(&u));
            acc.x += v.x; acc.y += v.y;
        }
    }
    const float dd = dinv[d];
    const float2 bv = reinterpret_cast<const float2*>(b)[lane];
    float2 o;
    o.x = fmaf(acc.x, dd, bv.x);
    o.y = fmaf(acc.y, dd, bv.y);
    reinterpret_cast<float2*>(A + (size_t)d * 64)[lane] = o;
}

// ---------------------------------------------------------------------------
// launch: GEMM1 (raw) overlaps the ENTIRE degree+CSR pipeline
// ---------------------------------------------------------------------------
extern "C" void kernel_launch(void* const* d_in, const int* in_sizes, int n_in,
                              void* d_out, int out_size) {
    const float* x = (const float*)d_in[0];
    const void* ei = d_in[1];
    const float* W1 = (const float*)d_in[2];
    const float* b1 = (const float*)d_in[3];
    const float* W2 = (const float*)d_in[4];
    const float* b2 = (const float*)d_in[5];
    const float* W3 = (const float*)d_in[6];
    const float* b3 = (const float*)d_in[7];
    float* out = (float*)d_out;

    const int n = in_sizes[0] / 128;
    const int e = in_sizes[1] / 2;

    __half *h16, *a16, *w1h, *w1l, *w2h, *w2l, *w3h, *w3l;
    float *dinv;
    int *cnt, *fill, *rowptr, *incl, *bsum, *csr;
    cudaGetSymbolAddress((void**)&h16, g_h16);
    cudaGetSymbolAddress((void**)&a16, g_a16);
    cudaGetSymbolAddress((void**)&dinv, g_dinv);
    cudaGetSymbolAddress((void**)&cnt, g_cnt);
    cudaGetSymbolAddress((void**)&fill, g_fill);
    cudaGetSymbolAddress((void**)&rowptr, g_rowptr);
    cudaGetSymbolAddress((void**)&incl, g_incl);
    cudaGetSymbolAddress((void**)&bsum, g_bsum);
    cudaGetSymbolAddress((void**)&csr, g_csr);
    cudaGetSymbolAddress((void**)&w1h, g_w1h);
    cudaGetSymbolAddress((void**)&w1l, g_w1l);
    cudaGetSymbolAddress((void**)&w2h, g_w2h);
    cudaGetSymbolAddress((void**)&w2l, g_w2l);
    cudaGetSymbolAddress((void**)&w3h, g_w3h);
    cudaGetSymbolAddress((void**)&w3l, g_w3l);

    const int T = 256;
    const int nb = (n + SCAN_B - 1) / SCAN_B;
    const int gemm_blocks = (n + 127) / 128;
    const int gather_blocks = (n * 32 + T - 1) / T;

    // weight split first (GEMM1 needs it), then fork
    wconv_all_kernel<<<160, 256>>>(W1, W2, W3, w1h, w1l, w2h, w2l, w3h, w3l);
    cudaEventRecord(g_ev_fork, 0);
    cudaStreamWaitEvent(g_s2, g_ev_fork, 0);

    // side stream: full degree + CSR pipeline
    probe_kernel<<<1, 1024, 0, g_s2>>>((const unsigned*)ei);
    zero1_kernel<<<(n + T - 1) / T, T, 0, g_s2>>>(cnt, n);
    count_kernel<<<(e + T - 1) / T, T, 0, g_s2>>>(ei, cnt, e, n);
    dinv_kernel<<<(n + T - 1) / T, T, 0, g_s2>>>(cnt, dinv, n);
    scan_block_kernel<<<nb, SCAN_B, 0, g_s2>>>(cnt, incl, bsum, n);
    scan_bsum_kernel<<<1, 256, 0, g_s2>>>(bsum, nb);
    scan_final_kernel<<<(n + T - 1) / T, T, 0, g_s2>>>(incl, cnt, bsum, rowptr,
                                                       fill, n);
    fill_csr_kernel<<<(e + T - 1) / T, T, 0, g_s2>>>(ei, fill, csr, e, n);
    cudaEventRecord(g_ev_join, g_s2);

    // main: GEMM1 raw (no dinv dependency)
    gemm_tc_kernel<128, false, false, false><<<gemm_blocks, 256>>>(
        x, w1h, w1l, dinv, h16, n);
    cudaStreamWaitEvent(0, g_ev_join, 0);

    // layer 1: weighted gather (raw H) -> a16
    gather128w_kernel<<<gather_blocks, T>>>(csr, rowptr, cnt, dinv, h16, b1, a16, n);

    // layer 2: half-in GEMM (prescale) -> h16 ; plain gather -> a16
    gemm_tc_kernel<128, true, true, true><<<gemm_blocks, 256>>>(
        a16, w2h, w2l, dinv, h16, n);
    gather128_kernel<<<gather_blocks, T>>>(csr, rowptr, cnt, dinv, h16, b2, a16, n);

    // layer 3: half-in GEMM (prescale, 64) -> h16 ; gather -> out (fp32)
    gemm_tc_kernel<64, true, true, true><<<gemm_blocks, 256>>>(
        a16, w3h, w3l, dinv, h16, n);
    gather64_kernel<<<gather_blocks, T>>>(csr, rowptr, cnt, dinv, h16, b3, out, n);
}

// round 16
// speedup vs baseline: 1.3526x; 1.1338x over previous
#include <cuda_runtime.h>
#include <cuda_fp16.h>
#include <cstdint>

// ---------------------------------------------------------------------------
// GCN 3-layer: CSR-gather over fp16 rows + single-fp16-W HMMA GEMM.
// Layer 1: GEMM writes RAW H (no dinv), fully overlaps degree/CSR pipeline;
//          gather1 applies dinv[s]*dinv[d] per edge.
// Layers 2/3: dinv prescaled in GEMM epilogue; gather is plain adds.
// Activations fp16 between layers; fp32 accumulate everywhere.
// ---------------------------------------------------------------------------

#define MAXN 100000
#define MAXE 1600000
#define SCAN_B 1024

__device__ __align__(16) __half g_h16[MAXN * 128];  // GEMM out
__device__ __align__(16) __half g_a16[MAXN * 128];  // gather out (fp16)
__device__ float g_dinv[MAXN];
__device__ int g_cnt[MAXN];
__device__ int g_fill[MAXN];
__device__ int g_rowptr[MAXN];
__device__ int g_incl[MAXN];
__device__ int g_bsum[256];
__device__ int g_csr[MAXE];
__device__ int g_is64;

__device__ __align__(16) __half g_w1[128 * 128];
__device__ __align__(16) __half g_w2[128 * 128];
__device__ __align__(16) __half g_w3[64 * 128];

static cudaStream_t g_s2;
static cudaEvent_t g_ev_fork, g_ev_join;
static bool g_stream_init = []() {
    cudaStreamCreateWithFlags(&g_s2, cudaStreamNonBlocking);
    cudaEventCreateWithFlags(&g_ev_fork, cudaEventDisableTiming);
    cudaEventCreateWithFlags(&g_ev_join, cudaEventDisableTiming);
    return true;
}();

// ---------------------------------------------------------------------------
// helpers
// ---------------------------------------------------------------------------
__device__ __forceinline__ void mma_f16(float* c, const unsigned* a,
                                        const unsigned* b) {
    asm("mma.sync.aligned.m16n8k16.row.col.f32.f16.f16.f32 "
        "{%0,%1,%2,%3},{%4,%5,%6,%7},{%8,%9},{%0,%1,%2,%3};"
        : "+f"(c[0]), "+f"(c[1]), "+f"(c[2]), "+f"(c[3])
        : "r"(a[0]), "r"(a[1]), "r"(a[2]), "r"(a[3]), "r"(b[0]), "r"(b[1]));
}

// single fused weight convert (all three W -> fp16)
__global__ void wconv_all_kernel(const float* __restrict__ W1,
                                 const float* __restrict__ W2,
                                 const float* __restrict__ W3,
                                 __half* __restrict__ w1, __half* __restrict__ w2,
                                 __half* __restrict__ w3) {
    int i = blockIdx.x * blockDim.x + threadIdx.x;
    if (i < 16384) {
        w1[i] = __float2half_rn(W1[i]);
    } else if (i < 32768) {
        int j = i - 16384;
        w2[j] = __float2half_rn(W2[j]);
    } else if (i < 40960) {
        int j = i - 32768;
        w3[j] = __float2half_rn(W3[j]);
    }
}

// fused zero + dtype probe: block 0 also probes ei (1024 samples)
__global__ void zero_probe_kernel(const unsigned* __restrict__ ei,
                                  int* __restrict__ cnt, int n) {
    int i = blockIdx.x * blockDim.x + threadIdx.x;
    if (blockIdx.x == 0) {
        if (threadIdx.x == 0) g_is64 = 1;
        __syncthreads();
        // 256 threads x 4 samples = 1024 probes
        for (int k = threadIdx.x; k < 1024; k += blockDim.x)
            if (ei[2 * k + 1] != 0) atomicAnd(&g_is64, 0);
    }
    if (i < n) cnt[i] = 0;
}

__device__ __forceinline__ void load_edge(const void* ei, int e, int g, int is64,
                                          int& s, int& d) {
    if (is64) {
        const long long* p = (const long long*)ei;
        s = (int)p[g];
        d = (int)p[e + g];
    } else {
        const int* p = (const int*)ei;
        s = p[g];
        d = p[e + g];
    }
}

// ---------------------------------------------------------------------------
// CSR build
// ---------------------------------------------------------------------------
// MLP-4 count: thread t handles edges t, t+Q, t+2Q, t+3Q (coalesced batches)
__global__ void count_kernel(const void* __restrict__ ei, int* __restrict__ cnt,
                             int e, int n) {
    int q = (e + 3) >> 2;
    int t = blockIdx.x * blockDim.x + threadIdx.x;
    if (t >= q) return;
    int is64 = g_is64;
    int d[4];
    int cnt_v = 0;
#pragma unroll
    for (int j = 0; j < 4; j++) {
        int i = t + j * q;
        if (i < e) {
            if (is64) d[cnt_v] = (int)((const long long*)ei)[e + i];
            else      d[cnt_v] = ((const int*)ei)[e + i];
            cnt_v++;
        }
    }
#pragma unroll
    for (int j = 0; j < 4; j++)
        if (j < cnt_v && (unsigned)d[j] < (unsigned)n) atomicAdd(&cnt[d[j]], 1);
}

__global__ void dinv_kernel(const int* __restrict__ cnt, float* __restrict__ dinv,
                            int n) {
    int i = blockIdx.x * blockDim.x + threadIdx.x;
    if (i < n) dinv[i] = rsqrtf((float)cnt[i] + 1.0f);
}

__global__ __launch_bounds__(SCAN_B) void scan_block_kernel(
    const int* __restrict__ cnt, int* __restrict__ incl, int* __restrict__ bsum,
    int n) {
    __shared__ int sm[SCAN_B];
    int i = blockIdx.x * SCAN_B + threadIdx.x;
    int v = (i < n) ? cnt[i] : 0;
    sm[threadIdx.x] = v;
    __syncthreads();
#pragma unroll
    for (int off = 1; off < SCAN_B; off <<= 1) {
        int t = (threadIdx.x >= off) ? sm[threadIdx.x - off] : 0;
        __syncthreads();
        sm[threadIdx.x] += t;
        __syncthreads();
    }
    if (i < n) incl[i] = sm[threadIdx.x];
    if (threadIdx.x == SCAN_B - 1) bsum[blockIdx.x] = sm[SCAN_B - 1];
}

__global__ __launch_bounds__(256) void scan_bsum_kernel(int* __restrict__ bsum,
                                                        int nb) {
    __shared__ int sm[256];
    int v = (threadIdx.x < nb) ? bsum[threadIdx.x] : 0;
    sm[threadIdx.x] = v;
    __syncthreads();
#pragma unroll
    for (int off = 1; off < 256; off <<= 1) {
        int t = (threadIdx.x >= off) ? sm[threadIdx.x - off] : 0;
        __syncthreads();
        sm[threadIdx.x] += t;
        __syncthreads();
    }
    if (threadIdx.x < nb) bsum[threadIdx.x] = sm[threadIdx.x] - v;
}

__global__ void scan_final_kernel(const int* __restrict__ incl,
                                  const int* __restrict__ cnt,
                                  const int* __restrict__ bsum,
                                  int* __restrict__ rowptr,
                                  int* __restrict__ fill, int n) {
    int i = blockIdx.x * blockDim.x + threadIdx.x;
    if (i < n) {
        int rp = incl[i] - cnt[i] + bsum[i / SCAN_B];
        rowptr[i] = rp;
        fill[i] = rp;
    }
}

// MLP-2 fill
__global__ void fill_csr_kernel(const void* __restrict__ ei,
                                int* __restrict__ fill, int* __restrict__ csr,
                                int e, int n) {
    int q = (e + 1) >> 1;
    int t = blockIdx.x * blockDim.x + threadIdx.x;
    if (t >= q) return;
    int is64 = g_is64;
    int s[2], d[2];
    int cnt_v = 0;
#pragma unroll
    for (int j = 0; j < 2; j++) {
        int i = t + j * q;
        if (i < e) {
            load_edge(ei, e, i, is64, s[cnt_v], d[cnt_v]);
            cnt_v++;
        }
    }
#pragma unroll
    for (int j = 0; j < 2; j++) {
        if (j < cnt_v && (unsigned)s[j] < (unsigned)n &&
            (unsigned)d[j] < (unsigned)n) {
            int pos = atomicAdd(&fill[d[j]], 1);
            csr[pos] = s[j];
        }
    }
}

// ---------------------------------------------------------------------------
// fp16 HMMA GEMM (single-fp16 W, 1 MMA per k16 step).
// HALFIN: X is __half; else fp32. PRESCALE: multiply rows by dinv in epilogue.
// ---------------------------------------------------------------------------
template <int COLS, bool RELU, bool PRESCALE, bool HALFIN>
__global__ __launch_bounds__(256) void gemm_tc_kernel(
    const void* __restrict__ Xv, const __half* __restrict__ W,
    const float* __restrict__ dinv, __half* __restrict__ H, int n) {
    __shared__ __half xs[128][40];
    __shared__ __half ws[COLS][40];

    constexpr int WM = (COLS == 128) ? 2 : 1;
    const int t = threadIdx.x;
    const int wid = t >> 5;
    const int lane = t & 31;
    const int gid = lane >> 2;
    const int tig = lane & 3;
    const int row0 = blockIdx.x * 128;

    int wm0, wn0;
    if (COLS == 128) { wm0 = (wid >> 1) * 32; wn0 = (wid & 1) * 64; }
    else             { wm0 = wid * 16;        wn0 = 0; }

    float acc[WM][8][4];
#pragma unroll
    for (int mt = 0; mt < WM; mt++)
#pragma unroll
        for (int nt = 0; nt < 8; nt++)
#pragma unroll
            for (int i = 0; i < 4; i++) acc[mt][nt][i] = 0.0f;

    for (int kb = 0; kb < 128; kb += 32) {
        if (HALFIN) {
            const unsigned* X2 = (const unsigned*)Xv;  // half2 view, 64/row
            for (int idx = t; idx < 128 * 16; idx += 256) {
                int r = idx >> 4, kk = idx & 15;
                int row = row0 + r;
                unsigned u = 0;
                if (row < n) {
                    u = X2[row * 64 + (kb >> 1) + kk];
                    if (RELU) {
                        __half2 z = __float2half2_rn(0.0f);
                        __half2 v = *reinterpret_cast<__half2*>(&u);
                        v = __hmax2(v, z);
                        u = *reinterpret_cast<unsigned*>(&v);
                    }
                }
                *reinterpret_cast<unsigned*>(&xs[r][2 * kk]) = u;
            }
        } else {
            const float* X = (const float*)Xv;
            for (int idx = t; idx < 128 * 32; idx += 256) {
                int r = idx >> 5, k = idx & 31;
                int row = row0 + r;
                float v = 0.0f;
                if (row < n) {
                    v = X[row * 128 + kb + k];
                    if (RELU) v = fmaxf(v, 0.0f);
                }
                xs[r][k] = __float2half_rn(v);
            }
        }
        for (int idx = t; idx < COLS * 32; idx += 256) {
            int c = idx >> 5, k = idx & 31;
            ws[c][k] = W[c * 128 + kb + k];
        }
        __syncthreads();

#pragma unroll
        for (int ks = 0; ks < 2; ks++) {
            const int k0 = ks * 16;
            unsigned ax[WM][4];
#pragma unroll
            for (int mt = 0; mt < WM; mt++) {
                int r = wm0 + mt * 16 + gid;
                ax[mt][0] = *reinterpret_cast<const unsigned*>(&xs[r][k0 + tig * 2]);
                ax[mt][1] = *reinterpret_cast<const unsigned*>(&xs[r + 8][k0 + tig * 2]);
                ax[mt][2] = *reinterpret_cast<const unsigned*>(&xs[r][k0 + tig * 2 + 8]);
                ax[mt][3] = *reinterpret_cast<const unsigned*>(&xs[r + 8][k0 + tig * 2 + 8]);
            }
#pragma unroll
            for (int nt = 0; nt < 8; nt++) {
                int c = wn0 + nt * 8 + gid;
                unsigned bw[2];
                bw[0] = *reinterpret_cast<const unsigned*>(&ws[c][k0 + tig * 2]);
                bw[1] = *reinterpret_cast<const unsigned*>(&ws[c][k0 + tig * 2 + 8]);
#pragma unroll
                for (int mt = 0; mt < WM; mt++)
                    mma_f16(acc[mt][nt], ax[mt], bw);
            }
        }
        __syncthreads();
    }

#pragma unroll
    for (int mt = 0; mt < WM; mt++) {
        int r = row0 + wm0 + mt * 16 + gid;
        float d0 = 1.0f, d1 = 1.0f;
        if (PRESCALE) {
            d0 = (r < n) ? dinv[r] : 0.0f;
            d1 = (r + 8 < n) ? dinv[r + 8] : 0.0f;
        }
#pragma unroll
        for (int nt = 0; nt < 8; nt++) {
            int c = wn0 + nt * 8 + tig * 2;
            if (r < n)
                *reinterpret_cast<__half2*>(H + (size_t)r * COLS + c) =
                    __floats2half2_rn(acc[mt][nt][0] * d0, acc[mt][nt][1] * d0);
            if (r + 8 < n)
                *reinterpret_cast<__half2*>(H + (size_t)(r + 8) * COLS + c) =
                    __floats2half2_rn(acc[mt][nt][2] * d1, acc[mt][nt][3] * d1);
        }
    }
}

// ---------------------------------------------------------------------------
// gather1 (weighted; raw H): A16[d] = fp16( b + dd^2*H[d] + sum w_e*H[s] )
// ---------------------------------------------------------------------------
__global__ __launch_bounds__(256) void gather128w_kernel(
    const int* __restrict__ csr, const int* __restrict__ rowptr,
    const int* __restrict__ cnt, const float* __restrict__ dinv,
    const __half* __restrict__ H, const float* __restrict__ b,
    __half* __restrict__ A, int n) {
    int d = (blockIdx.x * blockDim.x + threadIdx.x) >> 5;
    int lane = threadIdx.x & 31;
    if (d >= n) return;
    const int start = rowptr[d];
    const int c = cnt[d];
    const float dd = dinv[d];

    float4 acc;
    {
        float w0 = dd * dd;
        uint2 u = reinterpret_cast<const uint2*>(H + (size_t)d * 128)[lane];
        float2 lo = __half22float2(*reinterpret_cast<__half2*>(&u.x));
        float2 hi = __half22float2(*reinterpret_cast<__half2*>(&u.y));
        acc.x = lo.x * w0; acc.y = lo.y * w0; acc.z = hi.x * w0; acc.w = hi.y * w0;
    }

    for (int j0 = 0; j0 < c; j0 += 32) {
        int valid = j0 + lane < c;
        int s = valid ? csr[start + j0 + lane] : 0;
        float ws = valid ? dinv[s] * dd : 0.0f;
        int m = min(32, c - j0);
#pragma unroll 8
        for (int k = 0; k < m; k++) {
            int sk = __shfl_sync(0xffffffffu, s, k);
            float wk = __shfl_sync(0xffffffffu, ws, k);
            uint2 u = reinterpret_cast<const uint2*>(H + (size_t)sk * 128)[lane];
            float2 lo = __half22float2(*reinterpret_cast<__half2*>(&u.x));
            float2 hi = __half22float2(*reinterpret_cast<__half2*>(&u.y));
            acc.x = fmaf(lo.x, wk, acc.x);
            acc.y = fmaf(lo.y, wk, acc.y);
            acc.z = fmaf(hi.x, wk, acc.z);
            acc.w = fmaf(hi.y, wk, acc.w);
        }
    }
    const float4 bv = reinterpret_cast<const float4*>(b)[lane];
    uint2 o;
    __half2 o0 = __floats2half2_rn(acc.x + bv.x, acc.y + bv.y);
    __half2 o1 = __floats2half2_rn(acc.z + bv.z, acc.w + bv.w);
    o.x = *reinterpret_cast<unsigned*>(&o0);
    o.y = *reinterpret_cast<unsigned*>(&o1);
    reinterpret_cast<uint2*>(A + (size_t)d * 128)[lane] = o;
}

// gather (prescaled H): A16[d] = fp16( b + dd*( H'[d] + sum H'[s] ) )
__global__ __launch_bounds__(256) void gather128_kernel(
    const int* __restrict__ csr, const int* __restrict__ rowptr,
    const int* __restrict__ cnt, const float* __restrict__ dinv,
    const __half* __restrict__ H, const float* __restrict__ b,
    __half* __restrict__ A, int n) {
    int d = (blockIdx.x * blockDim.x + threadIdx.x) >> 5;
    int lane = threadIdx.x & 31;
    if (d >= n) return;
    const int start = rowptr[d];
    const int c = cnt[d];

    float4 acc;
    {
        uint2 u = reinterpret_cast<const uint2*>(H + (size_t)d * 128)[lane];
        float2 lo = __half22float2(*reinterpret_cast<__half2*>(&u.x));
        float2 hi = __half22float2(*reinterpret_cast<__half2*>(&u.y));
        acc.x = lo.x; acc.y = lo.y; acc.z = hi.x; acc.w = hi.y;
    }

    for (int j0 = 0; j0 < c; j0 += 32) {
        int s = (j0 + lane < c) ? csr[start + j0 + lane] : 0;
        int m = min(32, c - j0);
#pragma unroll 8
        for (int k = 0; k < m; k++) {
            int sk = __shfl_sync(0xffffffffu, s, k);
            uint2 u = reinterpret_cast<const uint2*>(H + (size_t)sk * 128)[lane];
            float2 lo = __half22float2(*reinterpret_cast<__half2*>(&u.x));
            float2 hi = __half22float2(*reinterpret_cast<__half2*>(&u.y));
            acc.x += lo.x; acc.y += lo.y; acc.z += hi.x; acc.w += hi.y;
        }
    }
    const float dd = dinv[d];
    const float4 bv = reinterpret_cast<const float4*>(b)[lane];
    uint2 o;
    __half2 o0 = __floats2half2_rn(fmaf(acc.x, dd, bv.x), fmaf(acc.y, dd, bv.y));
    __half2 o1 = __floats2half2_rn(fmaf(acc.z, dd, bv.z), fmaf(acc.w, dd, bv.w));
    o.x = *reinterpret_cast<unsigned*>(&o0);
    o.y = *reinterpret_cast<unsigned*>(&o1);
    reinterpret_cast<uint2*>(A + (size_t)d * 128)[lane] = o;
}

// final gather: fp32 out
__global__ __launch_bounds__(256) void gather64_kernel(
    const int* __restrict__ csr, const int* __restrict__ rowptr,
    const int* __restrict__ cnt, const float* __restrict__ dinv,
    const __half* __restrict__ H, const float* __restrict__ b,
    float* __restrict__ A, int n) {
    int d = (blockIdx.x * blockDim.x + threadIdx.x) >> 5;
    int lane = threadIdx.x & 31;
    if (d >= n) return;
    const int start = rowptr[d];
    const int c = cnt[d];

    float2 acc;
    {
        unsigned u = reinterpret_cast<const unsigned*>(H + (size_t)d * 64)[lane];
        float2 hv = __half22float2(*reinterpret_cast<__half2*>(&u));
        acc.x = hv.x; acc.y = hv.y;
    }

    for (int j0 = 0; j0 < c; j0 += 32) {
        int s = (j0 + lane < c) ? csr[start + j0 + lane] : 0;
        int m = min(32, c - j0);
#pragma unroll 8
        for (int k = 0; k < m; k++) {
            int sk = __shfl_sync(0xffffffffu, s, k);
            unsigned u = reinterpret_cast<const unsigned*>(H + (size_t)sk * 64)[lane];
            float2 v = __half22float2(*reinterpret_cast<__half2*>(&u));
            acc.x += v.x; acc.y += v.y;
        }
    }
    const float dd = dinv[d];
    const float2 bv = reinterpret_cast<const float2*>(b)[lane];
    float2 o;
    o.x = fmaf(acc.x, dd, bv.x);
    o.y = fmaf(acc.y, dd, bv.y);
    reinterpret_cast<float2*>(A + (size_t)d * 64)[lane] = o;
}

// ---------------------------------------------------------------------------
// launch: GEMM1 (raw) overlaps the entire degree+CSR pipeline
// ---------------------------------------------------------------------------
extern "C" void kernel_launch(void* const* d_in, const int* in_sizes, int n_in,
                              void* d_out, int out_size) {
    const float* x = (const float*)d_in[0];
    const void* ei = d_in[1];
    const float* W1 = (const float*)d_in[2];
    const float* b1 = (const float*)d_in[3];
    const float* W2 = (const float*)d_in[4];
    const float* b2 = (const float*)d_in[5];
    const float* W3 = (const float*)d_in[6];
    const float* b3 = (const float*)d_in[7];
    float* out = (float*)d_out;

    const int n = in_sizes[0] / 128;
    const int e = in_sizes[1] / 2;

    __half *h16, *a16, *w1, *w2, *w3;
    float *dinv;
    int *cnt, *fill, *rowptr, *incl, *bsum, *csr;
    cudaGetSymbolAddress((void**)&h16, g_h16);
    cudaGetSymbolAddress((void**)&a16, g_a16);
    cudaGetSymbolAddress((void**)&dinv, g_dinv);
    cudaGetSymbolAddress((void**)&cnt, g_cnt);
    cudaGetSymbolAddress((void**)&fill, g_fill);
    cudaGetSymbolAddress((void**)&rowptr, g_rowptr);
    cudaGetSymbolAddress((void**)&incl, g_incl);
    cudaGetSymbolAddress((void**)&bsum, g_bsum);
    cudaGetSymbolAddress((void**)&csr, g_csr);
    cudaGetSymbolAddress((void**)&w1, g_w1);
    cudaGetSymbolAddress((void**)&w2, g_w2);
    cudaGetSymbolAddress((void**)&w3, g_w3);

    const int T = 256;
    const int nb = (n + SCAN_B - 1) / SCAN_B;
    const int gemm_blocks = (n + 127) / 128;
    const int gather_blocks = (n * 32 + T - 1) / T;

    // weight convert first (GEMM1 needs it), then fork
    wconv_all_kernel<<<160, 256>>>(W1, W2, W3, w1, w2, w3);
    cudaEventRecord(g_ev_fork, 0);
    cudaStreamWaitEvent(g_s2, g_ev_fork, 0);

    // side stream: zero+probe, count(x4), dinv, scan, fill(x2)
    zero_probe_kernel<<<(n + T - 1) / T, T, 0, g_s2>>>((const unsigned*)ei, cnt, n);
    {
        int q = (e + 3) >> 2;
        count_kernel<<<(q + T - 1) / T, T, 0, g_s2>>>(ei, cnt, e, n);
    }
    dinv_kernel<<<(n + T - 1) / T, T, 0, g_s2>>>(cnt, dinv, n);
    scan_block_kernel<<<nb, SCAN_B, 0, g_s2>>>(cnt, incl, bsum, n);
    scan_bsum_kernel<<<1, 256, 0, g_s2>>>(bsum, nb);
    scan_final_kernel<<<(n + T - 1) / T, T, 0, g_s2>>>(incl, cnt, bsum, rowptr,
                                                       fill, n);
    {
        int q = (e + 1) >> 1;
        fill_csr_kernel<<<(q + T - 1) / T, T, 0, g_s2>>>(ei, fill, csr, e, n);
    }
    cudaEventRecord(g_ev_join, g_s2);

    // main: GEMM1 raw (no dinv dependency)
    gemm_tc_kernel<128, false, false, false><<<gemm_blocks, 256>>>(
        x, w1, dinv, h16, n);
    cudaStreamWaitEvent(0, g_ev_join, 0);

    // layer 1: weighted gather (raw H) -> a16
    gather128w_kernel<<<gather_blocks, T>>>(csr, rowptr, cnt, dinv, h16, b1, a16, n);

    // layer 2
    gemm_tc_kernel<128, true, true, true><<<gemm_blocks, 256>>>(
        a16, w2, dinv, h16, n);
    gather128_kernel<<<gather_blocks, T>>>(csr, rowptr, cnt, dinv, h16, b2, a16, n);

    // layer 3
    gemm_tc_kernel<64, true, true, true><<<gemm_blocks, 256>>>(
        a16, w3, dinv, h16, n);
    gather64_kernel<<<gather_blocks, T>>>(csr, rowptr, cnt, dinv, h16, b3, out, n);
}